// round 2
// baseline (speedup 1.0000x reference)
#include <cuda_runtime.h>
#include <math_constants.h>

#define N_NODES 50000
#define N_EDGES 1200000
#define N_GRAPHS 512
#define D1 64
#define NF 92
#define NG 50
#define BN_EPS 1e-5f
#define LOG2F_C 0.6931471805599453f

typedef unsigned long long ull;

// -------------------- device scratch --------------------
__device__ float g_out[N_NODES * D1];
__device__ float g_h[N_NODES * D1];
__device__ float g_agg[N_NODES * D1];
__device__ float g_C[N_EDGES];
__device__ float g_bnstats[2 * D1];
__device__ float g_pool[N_GRAPHS * D1];
__device__ float g_cnt[N_GRAPHS];
__device__ int   g_hist[N_NODES];     // histogram -> start offsets (bumped by scatter)
__device__ int   g_eperm[N_EDGES];    // edge ids sorted by dst

// -------------------- helpers --------------------
__device__ __forceinline__ ull ffma2(ull a, ull b, ull c) {
    ull d;
    asm("fma.rn.f32x2 %0, %1, %2, %3;" : "=l"(d) : "l"(a), "l"(b), "l"(c));
    return d;
}
__device__ __forceinline__ float f2lo(ull v) { return __uint_as_float((unsigned)(v & 0xffffffffull)); }
__device__ __forceinline__ float f2hi(ull v) { return __uint_as_float((unsigned)(v >> 32)); }

__device__ __forceinline__ float sspf(float v) {
    return fmaxf(v, 0.f) + __logf(1.f + __expf(-fabsf(v))) - LOG2F_C;
}

__device__ __forceinline__ void red4(float* p, float4 v) {
    asm volatile("red.global.add.v4.f32 [%0], {%1,%2,%3,%4};"
                 :: "l"(p), "f"(v.x), "f"(v.y), "f"(v.z), "f"(v.w) : "memory");
}

// =====================================================================
// counting sort by dst
// =====================================================================
__global__ void k_hist(const int* __restrict__ ei) {
    int i = blockIdx.x * blockDim.x + threadIdx.x;
    if (i < N_EDGES) atomicAdd(&g_hist[ei[N_EDGES + i]], 1);
}

__global__ __launch_bounds__(1024) void k_scan() {
    __shared__ int ss[1024];
    int t = threadIdx.x;
    int lo = t * 49;
    int hi = min(lo + 49, N_NODES);
    int s = 0;
    for (int b = lo; b < hi; b++) s += g_hist[b];
    ss[t] = s;
    __syncthreads();
    for (int off = 1; off < 1024; off <<= 1) {
        int v = (t >= off) ? ss[t - off] : 0;
        __syncthreads();
        ss[t] += v;
        __syncthreads();
    }
    int run = ss[t] - s;  // exclusive prefix
    for (int b = lo; b < hi; b++) {
        int c = g_hist[b];
        g_hist[b] = run;
        run += c;
    }
}

__global__ void k_scatter(const int* __restrict__ ei) {
    int i = blockIdx.x * blockDim.x + threadIdx.x;
    if (i < N_EDGES) {
        int pos = atomicAdd(&g_hist[ei[N_EDGES + i]], 1);
        g_eperm[pos] = i;
    }
}

// =====================================================================
// pre FC: out = relu(x @ pre_W.T + pre_b)
// =====================================================================
__global__ __launch_bounds__(256) void k_pre(const float* __restrict__ x,
                                             const float* __restrict__ W,
                                             const float* __restrict__ b) {
    __shared__ float sW[64 * 93];
    int tid = threadIdx.x;
    for (int i = tid; i < 64 * 92; i += 256) {
        int f = i / 92, k = i % 92;
        sW[f * 93 + k] = W[i];
    }
    __syncthreads();
    int lane = tid & 31;
    int warp = (blockIdx.x * blockDim.x + tid) >> 5;
    int nwarps = (gridDim.x * blockDim.x) >> 5;
    float b0 = b[lane], b1 = b[lane + 32];
    for (int n = warp; n < N_NODES; n += nwarps) {
        const float* xr = x + (size_t)n * NF;
        float x0 = xr[lane];
        float x1 = xr[32 + lane];
        float x2 = (lane < 28) ? xr[64 + lane] : 0.f;
        float a0 = b0, a1 = b1;
#pragma unroll
        for (int k = 0; k < NF; k++) {
            float src = (k < 32) ? x0 : ((k < 64) ? x1 : x2);
            float xv = __shfl_sync(0xffffffffu, src, k & 31);
            a0 = fmaf(xv, sW[lane * 93 + k], a0);
            a1 = fmaf(xv, sW[(lane + 32) * 93 + k], a1);
        }
        g_out[(size_t)n * D1 + lane] = fmaxf(a0, 0.f);
        g_out[(size_t)n * D1 + lane + 32] = fmaxf(a1, 0.f);
    }
}

__global__ void k_cutoff(const float* __restrict__ ew) {
    int i = blockIdx.x * blockDim.x + threadIdx.x;
    if (i < N_EDGES) g_C[i] = 0.5f * (cospif(ew[i] * 0.125f) + 1.f);
}

// =====================================================================
// lin1: g_h = g_out @ cf_W1.T  (unchanged from R1)
// =====================================================================
#define LIN1_SMEM ((4096 + 16384) * 4)
__global__ __launch_bounds__(256, 2) void k_lin1(const float* __restrict__ W) {
    extern __shared__ float sm[];
    float* sWt = sm;
    float* sA = sm + 4096;

    int tid = threadIdx.x;
    int tx = tid & 15, ty = tid >> 4;
    int n0 = blockIdx.x * 128;

    for (int i = tid; i < 64 * 64; i += 256) {
        int f = i >> 6, k = i & 63;
        sWt[k * 64 + f] = W[i];
    }
    for (int i = tid; i < 128 * 64; i += 256) {
        int e = i >> 6, k = i & 63;
        int n = n0 + e;
        float v = (n < N_NODES) ? g_out[n * D1 + k] : 0.f;
        *(float2*)&sA[e * 128 + 2 * k] = make_float2(v, v);
    }
    __syncthreads();

    ull acc[8][2];
#pragma unroll
    for (int ii = 0; ii < 8; ii++) { acc[ii][0] = 0ull; acc[ii][1] = 0ull; }
#pragma unroll
    for (int p = 0; p < 32; p++) {
        ulonglong2 b0 = *reinterpret_cast<const ulonglong2*>(&sWt[(2 * p) * 64 + 4 * tx]);
        ulonglong2 b1 = *reinterpret_cast<const ulonglong2*>(&sWt[(2 * p + 1) * 64 + 4 * tx]);
#pragma unroll
        for (int ii = 0; ii < 8; ii++) {
            ulonglong2 a = *reinterpret_cast<const ulonglong2*>(&sA[(ty + 16 * ii) * 128 + 4 * p]);
            acc[ii][0] = ffma2(a.x, b0.x, acc[ii][0]);
            acc[ii][1] = ffma2(a.x, b0.y, acc[ii][1]);
            acc[ii][0] = ffma2(a.y, b1.x, acc[ii][0]);
            acc[ii][1] = ffma2(a.y, b1.y, acc[ii][1]);
        }
    }
#pragma unroll
    for (int ii = 0; ii < 8; ii++) {
        int n = n0 + ty + 16 * ii;
        if (n < N_NODES) {
            float4 o;
            o.x = f2lo(acc[ii][0]); o.y = f2hi(acc[ii][0]);
            o.z = f2lo(acc[ii][1]); o.w = f2hi(acc[ii][1]);
            *(float4*)&g_h[n * D1 + 4 * tx] = o;
        }
    }
}

// =====================================================================
// k_edge v2: edge-pair f32x2 tiling + swizzled transposed hidden +
// conflict-free dup-weight chunks + dst-sorted run-compressed red.v4
//   thread: edges 8*ty .. 8*ty+7 (consecutive, dst-sorted), feats 4*tx .. +3
// =====================================================================
#define EDGE_SMEM_WORDS 23680
#define EDGE_SMEM (EDGE_SMEM_WORDS * 4)
__global__ __launch_bounds__(256, 2) void k_edge(const float* __restrict__ EA,
                                                 const int* __restrict__ ei,
                                                 const float* __restrict__ W1,
                                                 const float* __restrict__ bias1,
                                                 const float* __restrict__ W2,
                                                 const float* __restrict__ bias2) {
    extern __shared__ float sm[];
    float* sW1A = sm;             // [50][64]  feats {4tx,4tx+1} dup
    float* sW1B = sm + 3200;      // [50][64]  feats {4tx+2,4tx+3} dup
    float* sW2A = sm + 6400;      // [64][64]
    float* sW2B = sm + 10496;     // [64][64]
    float* sAT  = sm + 14592;     // [64][132]: phase1 EA^T rows 0..49, phase2 hidden^T (swizzled)
    float* sB1  = sm + 23040;
    float* sB2  = sm + 23104;
    float* sC   = sm + 23168;     // 128
    int*   sSrc = (int*)(sm + 23296);
    int*   sDst = sSrc + 128;
    int*   sEid = sDst + 128;

    int tid = threadIdx.x;
    int tx = tid & 15, ty = tid >> 4;
    int e0 = blockIdx.x * 128;

    if (tid < 128) sEid[tid] = g_eperm[e0 + tid];
    __syncthreads();

    // dup-weight staging, chunked so B LDS.128 lanes are 16B-consecutive
    for (int i = tid; i < 3200; i += 256) {
        int f = i / 50, k = i - f * 50;
        float v = W1[i];
        int j = f & 3;
        float* base = (j < 2) ? sW1A : sW1B;
        *(float2*)&base[k * 64 + (f >> 2) * 4 + (j & 1) * 2] = make_float2(v, v);
    }
    for (int i = tid; i < 4096; i += 256) {
        int f = i >> 6, k = i & 63;
        float v = W2[i];
        int j = f & 3;
        float* base = (j < 2) ? sW2A : sW2B;
        *(float2*)&base[k * 64 + (f >> 2) * 4 + (j & 1) * 2] = make_float2(v, v);
    }
    if (tid < 64) { sB1[tid] = bias1[tid]; sB2[tid] = bias2[tid]; }
    if (tid >= 128) {
        int t = tid - 128;
        int id = sEid[t];
        sC[t] = g_C[id];
        sSrc[t] = ei[id];
        sDst[t] = ei[N_EDGES + id];
    }
    // EA gather + transpose (2 threads per edge row)
    {
        int s = tid >> 1, h = tid & 1;
        int id = sEid[s];
        const float2* row = (const float2*)(EA + (size_t)id * NG);
        int jb = h ? 13 : 0, je = h ? 25 : 13;
        for (int j = jb; j < je; j++) {
            float2 v = row[j];
            sAT[(2 * j) * 132 + s] = v.x;
            sAT[(2 * j + 1) * 132 + s] = v.y;
        }
    }
    __syncthreads();

    // ---- phase 1: hidden = EA @ W1.T, K=50 ----
    ull acc[4][4];
#pragma unroll
    for (int p = 0; p < 4; p++)
#pragma unroll
        for (int j = 0; j < 4; j++) acc[p][j] = 0ull;

#pragma unroll 10
    for (int k = 0; k < 50; k++) {
        ulonglong2 a01 = *(const ulonglong2*)&sAT[k * 132 + 8 * ty];
        ulonglong2 a23 = *(const ulonglong2*)&sAT[k * 132 + 8 * ty + 4];
        ulonglong2 bA = *(const ulonglong2*)&sW1A[k * 64 + 4 * tx];
        ulonglong2 bB = *(const ulonglong2*)&sW1B[k * 64 + 4 * tx];
        acc[0][0] = ffma2(a01.x, bA.x, acc[0][0]);
        acc[0][1] = ffma2(a01.x, bA.y, acc[0][1]);
        acc[0][2] = ffma2(a01.x, bB.x, acc[0][2]);
        acc[0][3] = ffma2(a01.x, bB.y, acc[0][3]);
        acc[1][0] = ffma2(a01.y, bA.x, acc[1][0]);
        acc[1][1] = ffma2(a01.y, bA.y, acc[1][1]);
        acc[1][2] = ffma2(a01.y, bB.x, acc[1][2]);
        acc[1][3] = ffma2(a01.y, bB.y, acc[1][3]);
        acc[2][0] = ffma2(a23.x, bA.x, acc[2][0]);
        acc[2][1] = ffma2(a23.x, bA.y, acc[2][1]);
        acc[2][2] = ffma2(a23.x, bB.x, acc[2][2]);
        acc[2][3] = ffma2(a23.x, bB.y, acc[2][3]);
        acc[3][0] = ffma2(a23.y, bA.x, acc[3][0]);
        acc[3][1] = ffma2(a23.y, bA.y, acc[3][1]);
        acc[3][2] = ffma2(a23.y, bB.x, acc[3][2]);
        acc[3][3] = ffma2(a23.y, bB.y, acc[3][3]);
    }
    __syncthreads();  // done reading EA region

    // ssp + bias, store hidden transposed with XOR swizzle on 16B groups
#pragma unroll
    for (int j = 0; j < 4; j++) {
        int f = 4 * tx + j;
        float bj = sB1[f];
        int fx = f & 31;
#pragma unroll
        for (int p = 0; p < 4; p++) {
            float lo = sspf(f2lo(acc[p][j]) + bj);
            float hi = sspf(f2hi(acc[p][j]) + bj);
            int g = (2 * ty + (p >> 1)) ^ fx;
            *(float2*)&sAT[f * 132 + 4 * g + 2 * (p & 1)] = make_float2(lo, hi);
        }
    }
    __syncthreads();

    // ---- phase 2: w = hidden @ W2.T, K=64 ----
    ull wacc[4][4];
#pragma unroll
    for (int p = 0; p < 4; p++)
#pragma unroll
        for (int j = 0; j < 4; j++) wacc[p][j] = 0ull;

#pragma unroll 8
    for (int k = 0; k < 64; k++) {
        int kx = k & 31;
        ulonglong2 a01 = *(const ulonglong2*)&sAT[k * 132 + 4 * ((2 * ty) ^ kx)];
        ulonglong2 a23 = *(const ulonglong2*)&sAT[k * 132 + 4 * ((2 * ty + 1) ^ kx)];
        ulonglong2 bA = *(const ulonglong2*)&sW2A[k * 64 + 4 * tx];
        ulonglong2 bB = *(const ulonglong2*)&sW2B[k * 64 + 4 * tx];
        wacc[0][0] = ffma2(a01.x, bA.x, wacc[0][0]);
        wacc[0][1] = ffma2(a01.x, bA.y, wacc[0][1]);
        wacc[0][2] = ffma2(a01.x, bB.x, wacc[0][2]);
        wacc[0][3] = ffma2(a01.x, bB.y, wacc[0][3]);
        wacc[1][0] = ffma2(a01.y, bA.x, wacc[1][0]);
        wacc[1][1] = ffma2(a01.y, bA.y, wacc[1][1]);
        wacc[1][2] = ffma2(a01.y, bB.x, wacc[1][2]);
        wacc[1][3] = ffma2(a01.y, bB.y, wacc[1][3]);
        wacc[2][0] = ffma2(a23.x, bA.x, wacc[2][0]);
        wacc[2][1] = ffma2(a23.x, bA.y, wacc[2][1]);
        wacc[2][2] = ffma2(a23.x, bB.x, wacc[2][2]);
        wacc[2][3] = ffma2(a23.x, bB.y, wacc[2][3]);
        wacc[3][0] = ffma2(a23.y, bA.x, wacc[3][0]);
        wacc[3][1] = ffma2(a23.y, bA.y, wacc[3][1]);
        wacc[3][2] = ffma2(a23.y, bB.x, wacc[3][2]);
        wacc[3][3] = ffma2(a23.y, bB.y, wacc[3][3]);
    }

    // ---- phase 3: bias+cutoff+gather+run-compressed vectorized scatter ----
    float cb0 = sB2[4 * tx + 0], cb1 = sB2[4 * tx + 1];
    float cb2 = sB2[4 * tx + 2], cb3 = sB2[4 * tx + 3];
    int cur = -1;
    float4 racc = make_float4(0.f, 0.f, 0.f, 0.f);
#pragma unroll
    for (int ii = 0; ii < 8; ii++) {
        int p = ii >> 1, h = ii & 1;
        float w0 = (h ? f2hi(wacc[p][0]) : f2lo(wacc[p][0])) + cb0;
        float w1 = (h ? f2hi(wacc[p][1]) : f2lo(wacc[p][1])) + cb1;
        float w2 = (h ? f2hi(wacc[p][2]) : f2lo(wacc[p][2])) + cb2;
        float w3 = (h ? f2hi(wacc[p][3]) : f2lo(wacc[p][3])) + cb3;
        int e = 8 * ty + ii;
        float cc = sC[e];
        int sn = sSrc[e], dn = sDst[e];
        float4 hh = *(const float4*)&g_h[(size_t)sn * D1 + 4 * tx];
        float4 m = make_float4(w0 * cc * hh.x, w1 * cc * hh.y,
                               w2 * cc * hh.z, w3 * cc * hh.w);
        if (ii == 0) {
            cur = dn; racc = m;
        } else if (dn == cur) {
            racc.x += m.x; racc.y += m.y; racc.z += m.z; racc.w += m.w;
        } else {
            red4(&g_agg[(size_t)cur * D1 + 4 * tx], racc);
            cur = dn; racc = m;
        }
    }
    red4(&g_agg[(size_t)cur * D1 + 4 * tx], racc);
}

// =====================================================================
// node kernel (unchanged from R1)
// =====================================================================
#define NODE_SMEM ((4096 + 4096 + 16384 + 64 + 64 + 64 + 64) * 4)
__global__ __launch_bounds__(256, 2) void k_node(const float* __restrict__ Wa,
                                                 const float* __restrict__ ba,
                                                 const float* __restrict__ Wb,
                                                 const float* __restrict__ bb) {
    extern __shared__ float sm[];
    float* sWat = sm;
    float* sWbt = sm + 4096;
    float* sA = sm + 8192;
    float* sBa = sm + 24576;
    float* sBb = sBa + 64;
    float* sSum = sBb + 64;
    float* sSq = sSum + 64;

    int tid = threadIdx.x;
    int tx = tid & 15, ty = tid >> 4;
    int n0 = blockIdx.x * 128;

    for (int i = tid; i < 64 * 64; i += 256) {
        int f = i >> 6, k = i & 63;
        sWat[k * 64 + f] = Wa[i];
        sWbt[k * 64 + f] = Wb[i];
    }
    if (tid < 64) { sBa[tid] = ba[tid]; sBb[tid] = bb[tid]; sSum[tid] = 0.f; sSq[tid] = 0.f; }
    for (int i = tid; i < 128 * 64; i += 256) {
        int e = i >> 6, k = i & 63;
        int n = n0 + e;
        float v = (n < N_NODES) ? g_agg[n * D1 + k] : 0.f;
        *(float2*)&sA[e * 128 + 2 * k] = make_float2(v, v);
    }
    __syncthreads();

    ull acc[8][2];
#pragma unroll
    for (int ii = 0; ii < 8; ii++) { acc[ii][0] = 0ull; acc[ii][1] = 0ull; }
#pragma unroll
    for (int p = 0; p < 32; p++) {
        ulonglong2 b0 = *reinterpret_cast<const ulonglong2*>(&sWat[(2 * p) * 64 + 4 * tx]);
        ulonglong2 b1 = *reinterpret_cast<const ulonglong2*>(&sWat[(2 * p + 1) * 64 + 4 * tx]);
#pragma unroll
        for (int ii = 0; ii < 8; ii++) {
            ulonglong2 a = *reinterpret_cast<const ulonglong2*>(&sA[(ty + 16 * ii) * 128 + 4 * p]);
            acc[ii][0] = ffma2(a.x, b0.x, acc[ii][0]);
            acc[ii][1] = ffma2(a.x, b0.y, acc[ii][1]);
            acc[ii][0] = ffma2(a.y, b1.x, acc[ii][0]);
            acc[ii][1] = ffma2(a.y, b1.y, acc[ii][1]);
        }
    }
    __syncthreads();

    float bb0 = sBa[4 * tx + 0], bb1 = sBa[4 * tx + 1];
    float bb2 = sBa[4 * tx + 2], bb3 = sBa[4 * tx + 3];
#pragma unroll
    for (int ii = 0; ii < 8; ii++) {
        int e = ty + 16 * ii;
        float h0 = sspf(f2lo(acc[ii][0]) + bb0);
        float h1 = sspf(f2hi(acc[ii][0]) + bb1);
        float h2 = sspf(f2lo(acc[ii][1]) + bb2);
        float h3 = sspf(f2hi(acc[ii][1]) + bb3);
        float2* p = (float2*)&sA[e * 128 + 8 * tx];
        p[0] = make_float2(h0, h0);
        p[1] = make_float2(h1, h1);
        p[2] = make_float2(h2, h2);
        p[3] = make_float2(h3, h3);
    }
    __syncthreads();

    ull wacc[8][2];
#pragma unroll
    for (int ii = 0; ii < 8; ii++) { wacc[ii][0] = 0ull; wacc[ii][1] = 0ull; }
#pragma unroll
    for (int p = 0; p < 32; p++) {
        ulonglong2 b0 = *reinterpret_cast<const ulonglong2*>(&sWbt[(2 * p) * 64 + 4 * tx]);
        ulonglong2 b1 = *reinterpret_cast<const ulonglong2*>(&sWbt[(2 * p + 1) * 64 + 4 * tx]);
#pragma unroll
        for (int ii = 0; ii < 8; ii++) {
            ulonglong2 a = *reinterpret_cast<const ulonglong2*>(&sA[(ty + 16 * ii) * 128 + 4 * p]);
            wacc[ii][0] = ffma2(a.x, b0.x, wacc[ii][0]);
            wacc[ii][1] = ffma2(a.x, b0.y, wacc[ii][1]);
            wacc[ii][0] = ffma2(a.y, b1.x, wacc[ii][0]);
            wacc[ii][1] = ffma2(a.y, b1.y, wacc[ii][1]);
        }
    }

    float c0 = sBb[4 * tx + 0], c1 = sBb[4 * tx + 1];
    float c2 = sBb[4 * tx + 2], c3 = sBb[4 * tx + 3];
    float ps0 = 0.f, ps1 = 0.f, ps2 = 0.f, ps3 = 0.f;
    float pq0 = 0.f, pq1 = 0.f, pq2 = 0.f, pq3 = 0.f;
#pragma unroll
    for (int ii = 0; ii < 8; ii++) {
        int n = n0 + ty + 16 * ii;
        if (n < N_NODES) {
            float4 prev = *(const float4*)&g_out[n * D1 + 4 * tx];
            float r0 = f2lo(wacc[ii][0]) + c0 + prev.x;
            float r1 = f2hi(wacc[ii][0]) + c1 + prev.y;
            float r2 = f2lo(wacc[ii][1]) + c2 + prev.z;
            float r3 = f2hi(wacc[ii][1]) + c3 + prev.w;
            float4 o; o.x = r0; o.y = r1; o.z = r2; o.w = r3;
            *(float4*)&g_out[n * D1 + 4 * tx] = o;
            ps0 += r0; ps1 += r1; ps2 += r2; ps3 += r3;
            pq0 += r0 * r0; pq1 += r1 * r1; pq2 += r2 * r2; pq3 += r3 * r3;
        }
    }
    atomicAdd(&sSum[4 * tx + 0], ps0); atomicAdd(&sSum[4 * tx + 1], ps1);
    atomicAdd(&sSum[4 * tx + 2], ps2); atomicAdd(&sSum[4 * tx + 3], ps3);
    atomicAdd(&sSq[4 * tx + 0], pq0);  atomicAdd(&sSq[4 * tx + 1], pq1);
    atomicAdd(&sSq[4 * tx + 2], pq2);  atomicAdd(&sSq[4 * tx + 3], pq3);
    __syncthreads();
    if (tid < 64) {
        atomicAdd(&g_bnstats[tid], sSum[tid]);
        atomicAdd(&g_bnstats[64 + tid], sSq[tid]);
    }
}

__global__ void k_bn(const float* __restrict__ g, const float* __restrict__ b) {
    int idx = blockIdx.x * blockDim.x + threadIdx.x;
    if (idx >= N_NODES * D1) return;
    int f = idx & 63;
    const float invN = 1.f / (float)N_NODES;
    float mu = g_bnstats[f] * invN;
    float var = fmaxf(g_bnstats[64 + f] * invN - mu * mu, 0.f);
    float sc = rsqrtf(var + BN_EPS) * g[f];
    g_out[idx] = (g_out[idx] - mu) * sc + b[f];
}

__global__ void k_pool(const int* __restrict__ batch) {
    int idx = blockIdx.x * blockDim.x + threadIdx.x;
    if (idx >= N_NODES * D1) return;
    int n = idx >> 6, f = idx & 63;
    int bg = batch[n];
    atomicAdd(&g_pool[bg * D1 + f], g_out[idx]);
    if (f == 0) atomicAdd(&g_cnt[bg], 1.f);
}

__global__ void k_head(const float* __restrict__ postW, const float* __restrict__ postb,
                       const float* __restrict__ outW, const float* __restrict__ outb,
                       float* __restrict__ y) {
    int g = blockIdx.x;
    int f = threadIdx.x;
    __shared__ float sp[64];
    __shared__ float sr[2];
    float cnt = fmaxf(g_cnt[g], 1.f);
    sp[f] = g_pool[g * D1 + f] / cnt;
    __syncthreads();
    float a = postb[f];
#pragma unroll
    for (int k = 0; k < 64; k++) a = fmaf(sp[k], postW[f * 64 + k], a);
    float hp = fmaxf(a, 0.f) * outW[f];
#pragma unroll
    for (int o = 16; o > 0; o >>= 1) hp += __shfl_down_sync(0xffffffffu, hp, o);
    if ((f & 31) == 0) sr[f >> 5] = hp;
    __syncthreads();
    if (f == 0) y[g] = sr[0] + sr[1] + outb[0];
}

// =====================================================================
extern "C" void kernel_launch(void* const* d_in, const int* in_sizes, int n_in,
                              void* d_out, int out_size) {
    const float* x      = (const float*)d_in[0];
    const float* ew     = (const float*)d_in[1];
    const float* ea     = (const float*)d_in[2];
    const int*   ei     = (const int*)d_in[3];
    const int*   batch  = (const int*)d_in[4];
    const float* pre_W  = (const float*)d_in[5];
    const float* pre_b  = (const float*)d_in[6];
    const float* mlp_W1 = (const float*)d_in[7];
    const float* mlp_b1 = (const float*)d_in[8];
    const float* mlp_W2 = (const float*)d_in[9];
    const float* mlp_b2 = (const float*)d_in[10];
    const float* cf_W1  = (const float*)d_in[11];
    const float* cf_W2  = (const float*)d_in[12];
    const float* cf_b2  = (const float*)d_in[13];
    const float* int_W  = (const float*)d_in[14];
    const float* int_b  = (const float*)d_in[15];
    const float* bn_g   = (const float*)d_in[16];
    const float* bn_b   = (const float*)d_in[17];
    const float* post_W = (const float*)d_in[18];
    const float* post_b = (const float*)d_in[19];
    const float* out_W  = (const float*)d_in[20];
    const float* out_b  = (const float*)d_in[21];
    float* y = (float*)d_out;

    void *agg_p, *bn_p, *pool_p, *cnt_p, *hist_p;
    cudaGetSymbolAddress(&agg_p, g_agg);
    cudaGetSymbolAddress(&bn_p, g_bnstats);
    cudaGetSymbolAddress(&pool_p, g_pool);
    cudaGetSymbolAddress(&cnt_p, g_cnt);
    cudaGetSymbolAddress(&hist_p, g_hist);

    cudaFuncSetAttribute(k_edge, cudaFuncAttributeMaxDynamicSharedMemorySize, EDGE_SMEM);
    cudaFuncSetAttribute(k_node, cudaFuncAttributeMaxDynamicSharedMemorySize, NODE_SMEM);
    cudaFuncSetAttribute(k_lin1, cudaFuncAttributeMaxDynamicSharedMemorySize, LIN1_SMEM);

    // counting sort of edges by dst
    cudaMemsetAsync(hist_p, 0, N_NODES * sizeof(int));
    k_hist<<<(N_EDGES + 255) / 256, 256>>>(ei);
    k_scan<<<1, 1024>>>();
    k_scatter<<<(N_EDGES + 255) / 256, 256>>>(ei);

    k_pre<<<512, 256>>>(x, pre_W, pre_b);
    k_cutoff<<<(N_EDGES + 255) / 256, 256>>>(ew);
    cudaMemsetAsync(pool_p, 0, N_GRAPHS * D1 * sizeof(float));
    cudaMemsetAsync(cnt_p, 0, N_GRAPHS * sizeof(float));

    for (int l = 0; l < 3; l++) {
        k_lin1<<<(N_NODES + 127) / 128, 256, LIN1_SMEM>>>(cf_W1 + l * 64 * 64);
        cudaMemsetAsync(agg_p, 0, (size_t)N_NODES * D1 * sizeof(float));
        cudaMemsetAsync(bn_p, 0, 2 * D1 * sizeof(float));
        k_edge<<<N_EDGES / 128, 256, EDGE_SMEM>>>(ea, ei,
                                                  mlp_W1 + l * 64 * 50, mlp_b1 + l * 64,
                                                  mlp_W2 + l * 64 * 64, mlp_b2 + l * 64);
        k_node<<<(N_NODES + 127) / 128, 256, NODE_SMEM>>>(cf_W2 + l * 64 * 64, cf_b2 + l * 64,
                                                          int_W + l * 64 * 64, int_b + l * 64);
        k_bn<<<(N_NODES * D1 + 255) / 256, 256>>>(bn_g + l * 64, bn_b + l * 64);
    }

    k_pool<<<(N_NODES * D1 + 255) / 256, 256>>>(batch);
    k_head<<<N_GRAPHS, 64>>>(post_W, post_b, out_W, out_b, y);
}